// round 1
// baseline (speedup 1.0000x reference)
#include <cuda_runtime.h>
#include <math.h>

#define ED 1536
#define BN 64
#define TILE_R 16
#define KC 256
#define DC 256
#define NTHREADS 256

// Scratch (allocation-free): gamma-folded down-proj weights + per-b correction scalars
__device__ float g_wdg[BN * ED];
__device__ float g_S1[BN];
__device__ float g_S2[BN];

// ---------- packed f32x2 helpers ----------
typedef unsigned long long u64;
__device__ __forceinline__ u64 pk(float a, float b) {
    u64 r; asm("mov.b64 %0, {%1, %2};" : "=l"(r) : "f"(a), "f"(b)); return r;
}
__device__ __forceinline__ void f2fma(u64 &d, u64 a, u64 b) {
    asm("fma.rn.f32x2 %0, %1, %2, %0;" : "+l"(d) : "l"(a), "l"(b));
}
__device__ __forceinline__ float f2sum(u64 a) {
    float x, y; asm("mov.b64 {%0, %1}, %2;" : "=f"(x), "=f"(y) : "l"(a)); return x + y;
}

// ---------- prep: wdg = w_down * gamma; S1 = sum(gamma*w); S2 = sum(beta*w)+b_down ----------
__global__ void prep_kernel(const float* __restrict__ w_down,
                            const float* __restrict__ b_down,
                            const float* __restrict__ gamma,
                            const float* __restrict__ beta) {
    int b = blockIdx.x;
    int tid = threadIdx.x;
    float s1 = 0.f, s2 = 0.f;
    for (int k = tid; k < ED; k += blockDim.x) {
        float w = w_down[b * ED + k];
        float wg = w * gamma[k];
        g_wdg[b * ED + k] = wg;
        s1 += wg;
        s2 += beta[k] * w;
    }
    __shared__ float r1[256], r2[256];
    r1[tid] = s1; r2[tid] = s2;
    __syncthreads();
    for (int s = 128; s > 0; s >>= 1) {
        if (tid < s) { r1[tid] += r1[tid + s]; r2[tid] += r2[tid + s]; }
        __syncthreads();
    }
    if (tid == 0) { g_S1[b] = r1[0]; g_S2[b] = r2[0] + b_down[b]; }
}

// ---------- fused main kernel: 16 rows per CTA ----------
// smem layout (floats):
//   X  [TILE_R][ED]          24576  (raw x; later overwritten with pre-norm output)
//   W  union: down chunk [64][KC+4]=16640  /  up chunk [DC][68]=17408  -> 17408
//   H  [TILE_R][BN]           1024
//   ST [TILE_R][2]              32
#define SMEM_FLOATS (TILE_R * ED + 17408 + TILE_R * BN + TILE_R * 2)

__global__ void __launch_bounds__(NTHREADS, 1)
peft_kernel(const float* __restrict__ x,
            const float* __restrict__ w_up,
            const float* __restrict__ b_up,
            float* __restrict__ out) {
    extern __shared__ float smem[];
    float* X  = smem;
    float* W  = smem + TILE_R * ED;
    float* H  = W + 17408;
    float* ST = H + TILE_R * BN;

    const int tid  = threadIdx.x;
    const int warp = tid >> 5;
    const int lane = tid & 31;
    const long row0 = (long)blockIdx.x * TILE_R;

    // ---- stage x tile into smem (coalesced float4) ----
    const float4* xg = (const float4*)(x + row0 * ED);
    float4* X4 = (float4*)X;
    for (int i = tid; i < TILE_R * ED / 4; i += NTHREADS) X4[i] = xg[i];
    __syncthreads();

    // ---- LayerNorm stats: 8 warps x 2 rows ----
    for (int rr = 0; rr < 2; ++rr) {
        int r = warp * 2 + rr;
        float s = 0.f, q = 0.f;
        const float4* row = (const float4*)(X + r * ED);
        for (int j = lane; j < ED / 4; j += 32) {
            float4 v = row[j];
            s += v.x + v.y + v.z + v.w;
            q += v.x * v.x + v.y * v.y + v.z * v.z + v.w * v.w;
        }
        for (int o = 16; o; o >>= 1) {
            s += __shfl_xor_sync(0xFFFFFFFFu, s, o);
            q += __shfl_xor_sync(0xFFFFFFFFu, q, o);
        }
        if (lane == 0) {
            float m = s * (1.f / ED);
            float v = q * (1.f / ED) - m * m;
            ST[r * 2]     = m;
            ST[r * 2 + 1] = rsqrtf(v + 1e-5f);
        }
    }
    __syncthreads();

    // ---- down-proj: thread (b = tid&63, rg = tid>>6) owns h[rg*4..+3][b] ----
    const int b  = tid & 63;
    const int rg = tid >> 6;
    u64 acc[4] = {0ull, 0ull, 0ull, 0ull};

    for (int kc0 = 0; kc0 < ED; kc0 += KC) {
        // stage gamma-folded w_down chunk [64][KC] (padded stride KC+4)
        for (int i = tid * 4; i < BN * KC; i += NTHREADS * 4) {
            int bb = i >> 8;      // i / KC  (KC == 256)
            int kk = i & (KC - 1);
            float4 v = *(const float4*)(g_wdg + bb * ED + kc0 + kk);
            *(float4*)(W + bb * (KC + 4) + kk) = v;
        }
        __syncthreads();

        const float* Wb = W + b * (KC + 4);
        #pragma unroll 4
        for (int kk = 0; kk < KC; kk += 4) {
            float4 w4 = *(const float4*)(Wb + kk);          // conflict-free (stride 260f)
            u64 w01 = pk(w4.x, w4.y), w23 = pk(w4.z, w4.w);
            #pragma unroll
            for (int j = 0; j < 4; ++j) {
                float4 xv = *(const float4*)(X + (rg * 4 + j) * ED + kc0 + kk); // broadcast
                f2fma(acc[j], pk(xv.x, xv.y), w01);
                f2fma(acc[j], pk(xv.z, xv.w), w23);
            }
        }
        __syncthreads();
    }

    // finalize h + exact GELU
    {
        float S1 = g_S1[b], S2 = g_S2[b];
        #pragma unroll
        for (int j = 0; j < 4; ++j) {
            int r = rg * 4 + j;
            float mean = ST[r * 2], rstd = ST[r * 2 + 1];
            float hh = rstd * f2sum(acc[j]) - rstd * mean * S1 + S2;
            float g  = 0.5f * hh * (1.f + erff(hh * 0.70710678118654752f));
            H[r * BN + b] = g;
        }
    }
    __syncthreads();

    // ---- up-proj + residual (writes back into X in place) ----
    const int dd = tid & 63;
    for (int d0 = 0; d0 < ED; d0 += DC) {
        // stage w_up chunk [DC][64] (padded stride 68)
        for (int i = tid * 4; i < DC * BN; i += NTHREADS * 4) {
            int di = i >> 6;
            int bi = i & 63;
            float4 v = *(const float4*)(w_up + (long)(d0 + di) * BN + bi);
            *(float4*)(W + di * 68 + bi) = v;
        }
        __syncthreads();

        float bu[4];
        #pragma unroll
        for (int i = 0; i < 4; ++i) bu[i] = b_up[d0 + dd + i * 64];

        u64 acc2[4][4];
        #pragma unroll
        for (int j = 0; j < 4; ++j)
            #pragma unroll
            for (int i = 0; i < 4; ++i) acc2[j][i] = 0ull;

        for (int bb = 0; bb < BN; bb += 4) {
            u64 wp[4][2];
            #pragma unroll
            for (int i = 0; i < 4; ++i) {
                float4 wv = *(const float4*)(W + (dd + i * 64) * 68 + bb); // conflict-free (stride 68f)
                wp[i][0] = pk(wv.x, wv.y);
                wp[i][1] = pk(wv.z, wv.w);
            }
            #pragma unroll
            for (int j = 0; j < 4; ++j) {
                float4 hv = *(const float4*)(H + (rg * 4 + j) * BN + bb);  // broadcast
                u64 h01 = pk(hv.x, hv.y), h23 = pk(hv.z, hv.w);
                #pragma unroll
                for (int i = 0; i < 4; ++i) {
                    f2fma(acc2[j][i], h01, wp[i][0]);
                    f2fma(acc2[j][i], h23, wp[i][1]);
                }
            }
        }

        #pragma unroll
        for (int j = 0; j < 4; ++j) {
            int r = rg * 4 + j;
            #pragma unroll
            for (int i = 0; i < 4; ++i) {
                int d = d0 + dd + i * 64;
                float v = f2sum(acc2[j][i]) + bu[i] + X[r * ED + d];
                X[r * ED + d] = v;
            }
        }
        __syncthreads();
    }

    // ---- L2 normalize rows ----
    for (int rr = 0; rr < 2; ++rr) {
        int r = warp * 2 + rr;
        float q = 0.f;
        const float4* row = (const float4*)(X + r * ED);
        for (int j = lane; j < ED / 4; j += 32) {
            float4 v = row[j];
            q += v.x * v.x + v.y * v.y + v.z * v.z + v.w * v.w;
        }
        for (int o = 16; o; o >>= 1) q += __shfl_xor_sync(0xFFFFFFFFu, q, o);
        if (lane == 0) {
            float n = sqrtf(q);
            ST[r * 2] = 1.f / fmaxf(n, 1e-12f);
        }
    }
    __syncthreads();

    // ---- scaled write-out (coalesced float4) ----
    float4* og = (float4*)(out + row0 * ED);
    for (int i = tid; i < TILE_R * ED / 4; i += NTHREADS) {
        int r = i / (ED / 4);
        float sc = ST[r * 2];
        float4 v = X4[i];
        v.x *= sc; v.y *= sc; v.z *= sc; v.w *= sc;
        og[i] = v;
    }
}

extern "C" void kernel_launch(void* const* d_in, const int* in_sizes, int n_in,
                              void* d_out, int out_size) {
    const float* x      = (const float*)d_in[0];
    const float* w_down = (const float*)d_in[1];
    const float* b_down = (const float*)d_in[2];
    const float* w_up   = (const float*)d_in[3];
    const float* b_up   = (const float*)d_in[4];
    const float* gamma  = (const float*)d_in[5];
    const float* beta   = (const float*)d_in[6];
    float* out = (float*)d_out;

    const int n_rows = in_sizes[0] / ED;   // 32768

    cudaFuncSetAttribute(peft_kernel, cudaFuncAttributeMaxDynamicSharedMemorySize,
                         SMEM_FLOATS * (int)sizeof(float));

    prep_kernel<<<BN, 256>>>(w_down, b_down, gamma, beta);
    peft_kernel<<<n_rows / TILE_R, NTHREADS, SMEM_FLOATS * sizeof(float)>>>(x, w_up, b_up, out);
}

// round 2
// speedup vs baseline: 1.2003x; 1.2003x over previous
#include <cuda_runtime.h>
#include <math.h>

#define ED 1536
#define BN 64
#define TILE_R 16
#define NTHREADS 256
#define XS 1540            // padded X row stride (floats): 1540 % 32 == 4 -> de-conflicted
#define KCD 128            // down-proj k chunk
#define WDS 132            // down W row stride (132 % 32 == 4)
#define DCU 256            // up-proj d chunk
#define WUS 68             // up W row stride (68 % 32 == 4)

// Scratch (allocation-free): gamma-folded down-proj weights + per-b correction scalars
__device__ float g_wdg[BN * ED];
__device__ float g_S1[BN];
__device__ float g_S2[BN];

typedef unsigned long long u64;
__device__ __forceinline__ u64 pk(float a, float b) {
    u64 r; asm("mov.b64 %0, {%1, %2};" : "=l"(r) : "f"(a), "f"(b)); return r;
}
__device__ __forceinline__ void f2fma(u64 &d, u64 a, u64 b) {
    asm("fma.rn.f32x2 %0, %1, %2, %0;" : "+l"(d) : "l"(a), "l"(b));
}
__device__ __forceinline__ float f2sum(u64 a) {
    float x, y; asm("mov.b64 {%0, %1}, %2;" : "=f"(x), "=f"(y) : "l"(a)); return x + y;
}
__device__ __forceinline__ void cp16(float* dst_smem, const float* src) {
    unsigned a = (unsigned)__cvta_generic_to_shared(dst_smem);
    asm volatile("cp.async.cg.shared.global [%0], [%1], 16;\n" :: "r"(a), "l"(src));
}
#define CP_COMMIT() asm volatile("cp.async.commit_group;\n" ::: "memory")
#define CP_WAIT(n)  asm volatile("cp.async.wait_group %0;\n" :: "n"(n) : "memory")

// ---------- prep: wdg = w_down * gamma; S1 = sum(gamma*w); S2 = sum(beta*w)+b_down ----------
__global__ void prep_kernel(const float* __restrict__ w_down,
                            const float* __restrict__ b_down,
                            const float* __restrict__ gamma,
                            const float* __restrict__ beta) {
    int b = blockIdx.x;
    int tid = threadIdx.x;
    float s1 = 0.f, s2 = 0.f;
    for (int k = tid; k < ED; k += blockDim.x) {
        float w = w_down[b * ED + k];
        float wg = w * gamma[k];
        g_wdg[b * ED + k] = wg;
        s1 += wg;
        s2 += beta[k] * w;
    }
    __shared__ float r1[256], r2[256];
    r1[tid] = s1; r2[tid] = s2;
    __syncthreads();
    for (int s = 128; s > 0; s >>= 1) {
        if (tid < s) { r1[tid] += r1[tid + s]; r2[tid] += r2[tid + s]; }
        __syncthreads();
    }
    if (tid == 0) { g_S1[b] = r1[0]; g_S2[b] = r2[0] + b_down[b]; }
}

// smem layout (floats):
//   X  [16][XS]                 24640
//   W  max(2*64*WDS, 256*WUS) = 17408  (down double-buffer / up single)
//   H  [16][64]                  1024
//   P  partials                  4096
//   ST [16][2]                     32
#define SMEM_FLOATS (TILE_R * XS + 17408 + 1024 + 4096 + 32)

__global__ void __launch_bounds__(NTHREADS, 1)
peft_kernel(const float* __restrict__ x,
            const float* __restrict__ w_up,
            const float* __restrict__ b_up,
            float* __restrict__ out) {
    extern __shared__ float smem[];
    float* X  = smem;
    float* W  = smem + TILE_R * XS;
    float* H  = W + 17408;
    float* P  = H + 1024;
    float* ST = P + 4096;

    const int tid  = threadIdx.x;
    const int warp = tid >> 5;
    const int lane = tid & 31;
    const long row0 = (long)blockIdx.x * TILE_R;

    // ---- prologue: async-stage down-W chunk 0 (overlaps with X staging + stats) ----
    {
        #pragma unroll
        for (int n = 0; n < 8; ++n) {
            int idx = tid + n * NTHREADS;
            int bb = idx >> 5, kk4 = idx & 31;
            cp16(W + bb * WDS + kk4 * 4, g_wdg + bb * ED + kk4 * 4);
        }
        CP_COMMIT();
    }

    // ---- stage x tile into smem (coalesced float4, padded rows) ----
    const float4* xg = (const float4*)(x + row0 * ED);
    for (int i = tid; i < TILE_R * ED / 4; i += NTHREADS) {
        int r = i / (ED / 4), c4 = i % (ED / 4);
        *(float4*)(X + r * XS + c4 * 4) = xg[i];
    }
    __syncthreads();

    // ---- LayerNorm stats: 8 warps x 2 rows ----
    for (int rr = 0; rr < 2; ++rr) {
        int r = warp * 2 + rr;
        float s = 0.f, q = 0.f;
        const float4* row = (const float4*)(X + r * XS);
        for (int j = lane; j < ED / 4; j += 32) {
            float4 v = row[j];
            s += v.x + v.y + v.z + v.w;
            q += v.x * v.x + v.y * v.y + v.z * v.z + v.w * v.w;
        }
        for (int o = 16; o; o >>= 1) {
            s += __shfl_xor_sync(0xFFFFFFFFu, s, o);
            q += __shfl_xor_sync(0xFFFFFFFFu, q, o);
        }
        if (lane == 0) {
            float m = s * (1.f / ED);
            float v = q * (1.f / ED) - m * m;
            ST[r * 2]     = m;
            ST[r * 2 + 1] = rsqrtf(v + 1e-5f);
        }
    }

    // ---- down-proj: thread = (kg k-split, rg row-group, bg b-group) ----
    // k-split 4, each thread owns 4 rows x 4 b (b = bg + 16*i), acc packed over k.
    const int kg = tid >> 6;
    const int t  = tid & 63;
    const int rg = t >> 4;
    const int bg = t & 15;

    u64 acc[4][4];
    #pragma unroll
    for (int j = 0; j < 4; ++j)
        #pragma unroll
        for (int i = 0; i < 4; ++i) acc[j][i] = 0ull;

    const int NCH = ED / KCD;  // 12
    for (int c = 0; c < NCH; ++c) {
        if (c + 1 < NCH) {
            float* buf = W + ((c + 1) & 1) * (BN * WDS);
            #pragma unroll
            for (int n = 0; n < 8; ++n) {
                int idx = tid + n * NTHREADS;
                int bb = idx >> 5, kk4 = idx & 31;
                cp16(buf + bb * WDS + kk4 * 4, g_wdg + bb * ED + (c + 1) * KCD + kk4 * 4);
            }
            CP_COMMIT();
            CP_WAIT(1);
        } else {
            CP_WAIT(0);
        }
        __syncthreads();

        const float* Wb = W + (c & 1) * (BN * WDS);
        const float* Xb = X + c * KCD;
        const int k0 = kg * 32;
        #pragma unroll 2
        for (int kk = k0; kk < k0 + 32; kk += 4) {
            u64 w01[4], w23[4];
            #pragma unroll
            for (int i = 0; i < 4; ++i) {
                float4 wv = *(const float4*)(Wb + (bg + i * 16) * WDS + kk);
                w01[i] = pk(wv.x, wv.y); w23[i] = pk(wv.z, wv.w);
            }
            #pragma unroll
            for (int j = 0; j < 4; ++j) {
                float4 xv = *(const float4*)(Xb + (rg * 4 + j) * XS + kk);
                u64 x01 = pk(xv.x, xv.y), x23 = pk(xv.z, xv.w);
                #pragma unroll
                for (int i = 0; i < 4; ++i) {
                    f2fma(acc[j][i], x01, w01[i]);
                    f2fma(acc[j][i], x23, w23[i]);
                }
            }
        }
        __syncthreads();
    }

    // ---- reduce k-split partials, finalize h + exact GELU ----
    #pragma unroll
    for (int j = 0; j < 4; ++j)
        #pragma unroll
        for (int i = 0; i < 4; ++i)
            P[(kg * 64 + t) * 16 + j * 4 + i] = f2sum(acc[j][i]);
    __syncthreads();

    for (int o = tid; o < TILE_R * BN; o += NTHREADS) {
        int r = o >> 6, b = o & 63;
        int t2 = (r >> 2) * 16 + (b & 15);
        int idx = t2 * 16 + (r & 3) * 4 + (b >> 4);
        float val = P[idx] + P[idx + 1024] + P[idx + 2048] + P[idx + 3072];
        float mean = ST[r * 2], rstd = ST[r * 2 + 1];
        float hh = rstd * val - rstd * mean * g_S1[b] + g_S2[b];
        H[r * 64 + b] = 0.5f * hh * (1.f + erff(hh * 0.70710678118654752f));
    }

    // ---- up-proj: thread owns 8 rows x 2 d (d = dgu, dgu+128); acc packed over b ----
    const int rg2 = tid >> 7;          // 2 row-groups of 8 (uniform per warp)
    const int dgu = tid & 127;

    for (int d0 = 0; d0 < ED; d0 += DCU) {
        __syncthreads();               // H ready / prev compute & writeback done
        #pragma unroll
        for (int n = 0; n < 16; ++n) {
            int idx = tid + n * NTHREADS;
            int dl = idx >> 4, b4 = idx & 15;
            cp16(W + dl * WUS + b4 * 4, w_up + (long)(d0 + dl) * BN + b4 * 4);
        }
        CP_COMMIT();
        CP_WAIT(0);
        __syncthreads();

        float bu0 = b_up[d0 + dgu];
        float bu1 = b_up[d0 + dgu + 128];

        u64 acc2[8][2];
        #pragma unroll
        for (int rr = 0; rr < 8; ++rr) { acc2[rr][0] = 0ull; acc2[rr][1] = 0ull; }

        #pragma unroll 4
        for (int bb = 0; bb < BN; bb += 4) {
            float4 wv0 = *(const float4*)(W + dgu * WUS + bb);
            float4 wv1 = *(const float4*)(W + (dgu + 128) * WUS + bb);
            u64 wa0 = pk(wv0.x, wv0.y), wb0 = pk(wv0.z, wv0.w);
            u64 wa1 = pk(wv1.x, wv1.y), wb1 = pk(wv1.z, wv1.w);
            #pragma unroll
            for (int rr = 0; rr < 8; ++rr) {
                float4 hv = *(const float4*)(H + (rg2 * 8 + rr) * 64 + bb);
                u64 h01 = pk(hv.x, hv.y), h23 = pk(hv.z, hv.w);
                f2fma(acc2[rr][0], h01, wa0);
                f2fma(acc2[rr][0], h23, wb0);
                f2fma(acc2[rr][1], h01, wa1);
                f2fma(acc2[rr][1], h23, wb1);
            }
        }

        #pragma unroll
        for (int rr = 0; rr < 8; ++rr) {
            int r = rg2 * 8 + rr;
            float* Xr = X + r * XS + d0;
            float v0 = f2sum(acc2[rr][0]) + bu0 + Xr[dgu];
            float v1 = f2sum(acc2[rr][1]) + bu1 + Xr[dgu + 128];
            Xr[dgu] = v0;
            Xr[dgu + 128] = v1;
        }
    }
    __syncthreads();

    // ---- L2 normalize rows ----
    for (int rr = 0; rr < 2; ++rr) {
        int r = warp * 2 + rr;
        float q = 0.f;
        const float4* row = (const float4*)(X + r * XS);
        for (int j = lane; j < ED / 4; j += 32) {
            float4 v = row[j];
            q += v.x * v.x + v.y * v.y + v.z * v.z + v.w * v.w;
        }
        for (int o = 16; o; o >>= 1) q += __shfl_xor_sync(0xFFFFFFFFu, q, o);
        if (lane == 0) ST[r * 2] = 1.f / fmaxf(sqrtf(q), 1e-12f);
    }
    __syncthreads();

    // ---- scaled write-out (coalesced float4) ----
    float4* og = (float4*)(out + row0 * ED);
    for (int i = tid; i < TILE_R * ED / 4; i += NTHREADS) {
        int r = i / (ED / 4), c4 = i % (ED / 4);
        float sc = ST[r * 2];
        float4 v = *(const float4*)(X + r * XS + c4 * 4);
        v.x *= sc; v.y *= sc; v.z *= sc; v.w *= sc;
        og[i] = v;
    }
}

extern "C" void kernel_launch(void* const* d_in, const int* in_sizes, int n_in,
                              void* d_out, int out_size) {
    const float* x      = (const float*)d_in[0];
    const float* w_down = (const float*)d_in[1];
    const float* b_down = (const float*)d_in[2];
    const float* w_up   = (const float*)d_in[3];
    const float* b_up   = (const float*)d_in[4];
    const float* gamma  = (const float*)d_in[5];
    const float* beta   = (const float*)d_in[6];
    float* out = (float*)d_out;

    const int n_rows = in_sizes[0] / ED;   // 32768

    cudaFuncSetAttribute(peft_kernel, cudaFuncAttributeMaxDynamicSharedMemorySize,
                         SMEM_FLOATS * (int)sizeof(float));

    prep_kernel<<<BN, 256>>>(w_down, b_down, gamma, beta);
    peft_kernel<<<n_rows / TILE_R, NTHREADS, SMEM_FLOATS * sizeof(float)>>>(x, w_up, b_up, out);
}